// round 1
// baseline (speedup 1.0000x reference)
#include <cuda_runtime.h>
#include <cuda_bf16.h>

#define PP     76800     // H*W
#define HH     240
#define WW     320
#define NC     22        // classes
#define NQ     300       // query points (15*20)
#define QW     20        // queries per row
#define QSKIP  16
#define EPSF   1e-6f

#define CHUNK    256
#define BTHREADS 320
#define CPAD     23      // padded class stride (gcd(23,32)=1)

// ---------------- device scratch (persistent; re-initialized every launch) ----
__device__ float4 g_pix[PP];         // ux, uy, px, py
__device__ float  g_dz[PP];
__device__ float  g_acc[NQ * NC];    // vote accumulator
__device__ float  g_clsCount[NC];
__device__ int    g_bestQ[NC];
__device__ float  g_bestV[NC];
__device__ float  g_cnt[NC];
__device__ float  g_zsum[NC];

// ---------------- shared inlier test (must be identical in k_vote / k_zsum) ---
__device__ __forceinline__ bool inlier_test(float qx, float qy, float4 pv) {
    float cx = qx - pv.z;
    float cy = qy - pv.w;
    float cn = sqrtf(cx * cx + cy * cy) + EPSF;
    float dt = cx * pv.x + cy * pv.y;
    return dt > 0.9f * cn;           // == (dt/cn > 0.9) up to 1 ulp
}

// ---------------- kernel 0: zero the accumulators -----------------------------
__global__ void k_init() {
    int i = blockIdx.x * blockDim.x + threadIdx.x;
    if (i < NQ * NC) g_acc[i] = 0.0f;
    if (i < NC) { g_clsCount[i] = 0.0f; g_cnt[i] = 0.0f; g_zsum[i] = 0.0f; }
}

// ---------------- kernel 1: per-pixel direction + class counts ----------------
__global__ void k_pre(const int* __restrict__ label, const float* __restrict__ vp) {
    __shared__ int sCnt[NC];
    int t = threadIdx.x;
    if (t < NC) sCnt[t] = 0;
    __syncthreads();

    int p = blockIdx.x * blockDim.x + t;   // grid sized exactly PP
    int lab = label[p];
    atomicAdd(&sCnt[lab], 1);

    float ux = 0.0f, uy = 0.0f, dz = 0.0f;
    if (lab > 0) {
        float dx = vp[(3 * lab + 0) * PP + p];
        float dy = vp[(3 * lab + 1) * PP + p];
        dz       = vp[(3 * lab + 2) * PP + p];
        float dn = sqrtf(dx * dx + dy * dy) + EPSF;
        ux = dx / dn;
        uy = dy / dn;
    }
    g_pix[p] = make_float4(ux, uy, (float)(p % WW), (float)(p / WW));
    g_dz[p]  = dz;

    __syncthreads();
    if (t < NC && sCnt[t]) atomicAdd(&g_clsCount[t], (float)sCnt[t]);
}

// ---------------- kernel 2: the O(Q*P) vote accumulation ----------------------
// One thread per query point; each block processes a 256-pixel chunk staged in
// smem; per-thread private smem histogram row -> no atomics in the hot loop.
__global__ void __launch_bounds__(BTHREADS) k_vote(const int* __restrict__ label) {
    __shared__ float  sAcc[NQ * CPAD];   // 27600 B
    __shared__ float4 sPix[CHUNK];       //  4096 B
    __shared__ int    sLab[CHUNK];       //  1024 B

    int t = threadIdx.x;
    for (int i = t; i < NQ * CPAD; i += BTHREADS) sAcc[i] = 0.0f;
    int base = blockIdx.x * CHUNK;
    for (int i = t; i < CHUNK; i += BTHREADS) {
        sPix[i] = g_pix[base + i];
        sLab[i] = label[base + i];
    }
    __syncthreads();

    if (t < NQ) {
        float qx = (float)((t % QW) * QSKIP);
        float qy = (float)((t / QW) * QSKIP);
        float* myAcc = &sAcc[t * CPAD];
        #pragma unroll 4
        for (int i = 0; i < CHUNK; i++) {
            float4 pv = sPix[i];                 // smem broadcast
            if (inlier_test(qx, qy, pv))
                myAcc[sLab[i]] += 1.0f;          // private row: no atomic
        }
    }
    __syncthreads();

    if (t < NQ) {
        #pragma unroll
        for (int c = 0; c < NC; c++) {
            float v = sAcc[t * CPAD + c];
            if (v != 0.0f) atomicAdd(&g_acc[t * NC + c], v);  // exact int sums
        }
    }
}

// ---------------- kernel 3: per-class argmax over queries (first-index ties) --
__global__ void k_argmax() {
    int warp = threadIdx.x >> 5;   // class
    int lane = threadIdx.x & 31;
    if (warp >= NC) return;

    float best = -1.0f;
    int   bq   = 0;
    for (int q = lane; q < NQ; q += 32) {        // increasing q: strict > keeps first
        float v = g_acc[q * NC + warp];
        if (v > best) { best = v; bq = q; }
    }
    #pragma unroll
    for (int off = 16; off; off >>= 1) {
        float ov = __shfl_down_sync(0xffffffffu, best, off);
        int   oq = __shfl_down_sync(0xffffffffu, bq,   off);
        if (ov > best || (ov == best && oq < bq)) { best = ov; bq = oq; }
    }
    if (lane == 0) { g_bestQ[warp] = bq; g_bestV[warp] = best; }
}

// ---------------- kernel 4: per-class inlier count + z-sum at best query ------
__global__ void k_zsum(const int* __restrict__ label) {
    __shared__ float sCnt[NC], sZ[NC];
    __shared__ int   sQ[NC];
    int t = threadIdx.x;
    if (t < NC) { sCnt[t] = 0.0f; sZ[t] = 0.0f; sQ[t] = g_bestQ[t]; }
    __syncthreads();

    int p = blockIdx.x * blockDim.x + t;
    int lab = label[p];
    if (lab > 0) {
        int q = sQ[lab];
        float qx = (float)((q % QW) * QSKIP);
        float qy = (float)((q / QW) * QSKIP);
        float4 pv = g_pix[p];
        if (inlier_test(qx, qy, pv)) {
            atomicAdd(&sCnt[lab], 1.0f);
            atomicAdd(&sZ[lab], g_dz[p]);
        }
    }
    __syncthreads();
    if (t < NC) {
        if (sCnt[t] != 0.0f) atomicAdd(&g_cnt[t], sCnt[t]);
        if (sZ[t]   != 0.0f) atomicAdd(&g_zsum[t], sZ[t]);
    }
}

// ---------------- kernel 5: assemble the (1, 22, 14) output -------------------
__global__ void k_final(const float* __restrict__ extents,
                        const float* __restrict__ poses,
                        const float* __restrict__ mdata,
                        float* __restrict__ out) {
    int c = threadIdx.x;
    if (c >= NC) return;

    float fx  = mdata[0] + EPSF;
    float fy  = mdata[4] + EPSF;
    float ppx = mdata[2];
    float ppy = mdata[5];

    float bv = g_bestV[c];
    int   bq = g_bestQ[c];
    float bx = (float)((bq % QW) * QSKIP);
    float by = (float)((bq / QW) * QSKIP);

    float cc  = g_clsCount[c];
    float cnt = g_cnt[c];
    float z   = g_zsum[c] / (cnt + EPSF);

    float ex = extents[c * 3 + 0];
    float ey = extents[c * 3 + 1];
    float ez = extents[c * 3 + 2];
    float half = 0.5f * sqrtf(ex * ex + ey * ey + ez * ez);

    float zsafe = (fabsf(z) > EPSF) ? z : EPSF;
    float r = fx * half / zsafe;

    bool valid = (bv >= 50.0f) && (cc >= 500.0f) && (bv / (cc + EPSF) >= 0.02f);
    float score = valid ? bv : 0.0f;

    float* o = out + c * 14;
    o[0]  = 0.0f;
    o[1]  = (float)c;
    o[2]  = bx - r;
    o[3]  = by - r;
    o[4]  = bx + r;
    o[5]  = by + r;
    o[6]  = score;
    o[7]  = poses[c * 13 + 6];
    o[8]  = poses[c * 13 + 7];
    o[9]  = poses[c * 13 + 8];
    o[10] = poses[c * 13 + 9];
    o[11] = (bx - ppx) * z / fx;
    o[12] = (by - ppy) * z / fy;
    o[13] = z;
}

// ---------------- launch ------------------------------------------------------
extern "C" void kernel_launch(void* const* d_in, const int* in_sizes, int n_in,
                              void* d_out, int out_size) {
    const int*   label   = (const int*)  d_in[0];   // (1,240,320) int32
    const float* vp      = (const float*)d_in[1];   // (1,66,240,320) f32
    const float* extents = (const float*)d_in[2];   // (22,3) f32
    const float* poses   = (const float*)d_in[3];   // (22,13) f32
    const float* mdata   = (const float*)d_in[4];   // (1,9) f32
    float*       out     = (float*)d_out;           // (1,22,14) f32

    k_init  <<<(NQ * NC + 255) / 256, 256>>>();
    k_pre   <<<PP / 256, 256>>>(label, vp);
    k_vote  <<<PP / CHUNK, BTHREADS>>>(label);
    k_argmax<<<1, NC * 32>>>();
    k_zsum  <<<PP / 256, 256>>>(label);
    k_final <<<1, 32>>>(extents, poses, mdata, out);
}

// round 2
// speedup vs baseline: 1.5049x; 1.5049x over previous
#include <cuda_runtime.h>
#include <cuda_bf16.h>

#define PP     76800     // H*W
#define HH     240
#define WW     320
#define NC     22        // classes
#define NCP    11        // class pairs (u64 packing)
#define NQ     300       // query points (15*20)
#define QW     20        // queries per row
#define QSKIP  16
#define EPSF   1e-6f
#define C1F    (0.9f * 1e-6f)

#define CPAD   23        // padded class stride
#define VTHR   320       // k_vote threads
#define VROWS  2         // rows per vote block
#define VBLKS  (HH / VROWS)   // 120

// ---------------- device scratch --------------------------------------------
__device__ float4             g_pix[PP];          // ux, uy, dz, lab(bits)
__device__ unsigned long long g_accP[NQ * NCP];   // packed vote counts
__device__ int                g_clsCnt[NC];
__device__ int                g_bestQ[NC];
__device__ float              g_bestV[NC];
__device__ float              g_zsum[NC];

// ---------------- shared inlier test (identical rounding in vote & zsum) -----
// Equivalent (in reals) to  (cx*ux+cy*uy)/(sqrt(cx^2+cy^2)+eps) > 0.9
__device__ __forceinline__ bool itest(float cx, float cy, float ux, float uy) {
    float rhs = fmaf(cx * cx, 0.81f, (0.81f * cy) * cy);
    float t   = fmaf(cx, ux, fmaf(cy, uy, -C1F));
    return t * fabsf(t) > rhs;
}

// ---------------- kernel 1: per-pixel dir + zero accumulators ----------------
__global__ void k_pre(const int* __restrict__ label, const float* __restrict__ vp) {
    int t = threadIdx.x;
    int p = blockIdx.x * 256 + t;             // grid covers PP exactly
    int gid = p;
    if (gid < NQ * NCP) g_accP[gid] = 0ULL;
    if (gid < NC) { g_clsCnt[gid] = 0; g_zsum[gid] = 0.0f; }

    int lab = label[p];
    float ux = 0.0f, uy = 0.0f, dz = 0.0f;
    if (lab > 0) {
        float dx = vp[(3 * lab + 0) * PP + p];
        float dy = vp[(3 * lab + 1) * PP + p];
        dz       = vp[(3 * lab + 2) * PP + p];
        float dn = sqrtf(dx * dx + dy * dy) + EPSF;
        ux = dx / dn;
        uy = dy / dn;
    }
    g_pix[p] = make_float4(ux, uy, dz, __int_as_float(lab));
}

// ---------------- kernel 2: O(Q*P) vote accumulation -------------------------
// 120 blocks, each owns 2 image rows (640 px). One thread per query point.
// cy loop-invariant per row; cx exact fp induction. u16 private histogram.
__global__ void __launch_bounds__(VTHR) k_vote() {
    __shared__ float4         sPix[VROWS * WW];        // 10.25 KB
    __shared__ unsigned short sCnt[NQ * CPAD];         // 13.8 KB
    __shared__ int            sCC[NC];

    int t = threadIdx.x;
    for (int i = t; i < NQ * CPAD; i += VTHR) sCnt[i] = 0;
    if (t < NC) sCC[t] = 0;
    __syncthreads();

    int base = blockIdx.x * (VROWS * WW);
    for (int i = t; i < VROWS * WW; i += VTHR) {
        float4 pv = g_pix[base + i];
        sPix[i] = pv;
        int lab = __float_as_int(pv.w);
        atomicAdd(&sCC[lab], 1);                        // class counts (exact)
    }
    __syncthreads();

    if (t < NQ) {
        float qx = (float)((t % QW) * QSKIP);
        float qy = (float)((t / QW) * QSKIP);
        unsigned short* myC = &sCnt[t * CPAD];
        #pragma unroll
        for (int rr = 0; rr < VROWS; rr++) {
            float cy = qy - (float)(blockIdx.x * VROWS + rr);
            const float4* sp = &sPix[rr * WW];
            float cx = qx;
            #pragma unroll 4
            for (int i = 0; i < WW; i++) {
                float4 pv = sp[i];                      // smem broadcast
                if (itest(cx, cy, pv.x, pv.y))
                    myC[__float_as_int(pv.w)] += 1;     // private row, no atomic
                cx -= 1.0f;                             // exact small ints
            }
        }
    }
    __syncthreads();

    // flush: pack class pairs into one u64 RED each (counts sum exactly)
    if (t < NQ) {
        #pragma unroll
        for (int c = 0; c < NCP; c++) {
            unsigned long long lo = sCnt[t * CPAD + 2 * c];
            unsigned long long hi = sCnt[t * CPAD + 2 * c + 1];
            unsigned long long v  = lo | (hi << 32);
            if (v) atomicAdd(&g_accP[t * NCP + c], v);
        }
    }
    if (t < NC) {
        int cc = sCC[t];
        if (cc) atomicAdd(&g_clsCnt[t], cc);
    }
}

// ---------------- kernel 3: per-class argmax (smem-staged, coalesced) --------
__global__ void k_argmax() {
    __shared__ float sA[NQ * NC];     // 26.4 KB, [q][c]
    int t = threadIdx.x;              // 704 threads = 22 warps
    for (int i = t; i < NQ * NCP; i += NC * 32) {
        unsigned long long v = g_accP[i];               // coalesced
        int q = i / NCP, c = i % NCP;
        *reinterpret_cast<float2*>(&sA[q * NC + 2 * c]) =
            make_float2((float)(unsigned int)v, (float)(unsigned int)(v >> 32));
    }
    __syncthreads();

    int w    = t >> 5;   // class
    int lane = t & 31;
    float best = -1.0f;
    int   bq   = 0;
    for (int q = lane; q < NQ; q += 32) {               // ascending: first-max tie
        float v = sA[q * NC + w];
        if (v > best) { best = v; bq = q; }
    }
    #pragma unroll
    for (int off = 16; off; off >>= 1) {
        float ov = __shfl_down_sync(0xffffffffu, best, off);
        int   oq = __shfl_down_sync(0xffffffffu, bq,   off);
        if (ov > best || (ov == best && oq < bq)) { best = ov; bq = oq; }
    }
    if (lane == 0) { g_bestQ[w] = bq; g_bestV[w] = best; }
}

// ---------------- kernel 4: z-sum at best query (count == bestV, not needed) -
__global__ void k_zsum() {
    __shared__ float sZ[NC];
    __shared__ int   sQ[NC];
    int t = threadIdx.x;
    if (t < NC) { sZ[t] = 0.0f; sQ[t] = g_bestQ[t]; }
    __syncthreads();

    int p = blockIdx.x * 256 + t;
    float4 pv = g_pix[p];
    int lab = __float_as_int(pv.w);
    if (lab > 0) {
        int q = sQ[lab];
        float qx = (float)((q % QW) * QSKIP);
        float qy = (float)((q / QW) * QSKIP);
        float cx = qx - (float)(p % WW);
        float cy = qy - (float)(p / WW);
        if (itest(cx, cy, pv.x, pv.y))                  // same rounding as k_vote
            atomicAdd(&sZ[lab], pv.z);
    }
    __syncthreads();
    if (t < NC && sZ[t] != 0.0f) atomicAdd(&g_zsum[t], sZ[t]);
}

// ---------------- kernel 5: assemble the (1, 22, 14) output ------------------
__global__ void k_final(const float* __restrict__ extents,
                        const float* __restrict__ poses,
                        const float* __restrict__ mdata,
                        float* __restrict__ out) {
    int c = threadIdx.x;
    if (c >= NC) return;

    float fx  = mdata[0] + EPSF;
    float fy  = mdata[4] + EPSF;
    float ppx = mdata[2];
    float ppy = mdata[5];

    float bv = g_bestV[c];
    int   bq = g_bestQ[c];
    float bx = (float)((bq % QW) * QSKIP);
    float by = (float)((bq / QW) * QSKIP);

    float cc = (float)g_clsCnt[c];
    float z  = g_zsum[c] / (bv + EPSF);    // cnt == best_votes (exact identity)

    float ex = extents[c * 3 + 0];
    float ey = extents[c * 3 + 1];
    float ez = extents[c * 3 + 2];
    float half = 0.5f * sqrtf(ex * ex + ey * ey + ez * ez);

    float zsafe = (fabsf(z) > EPSF) ? z : EPSF;
    float r = fx * half / zsafe;

    bool valid = (bv >= 50.0f) && (cc >= 500.0f) && (bv / (cc + EPSF) >= 0.02f);
    float score = valid ? bv : 0.0f;

    float* o = out + c * 14;
    o[0]  = 0.0f;
    o[1]  = (float)c;
    o[2]  = bx - r;
    o[3]  = by - r;
    o[4]  = bx + r;
    o[5]  = by + r;
    o[6]  = score;
    o[7]  = poses[c * 13 + 6];
    o[8]  = poses[c * 13 + 7];
    o[9]  = poses[c * 13 + 8];
    o[10] = poses[c * 13 + 9];
    o[11] = (bx - ppx) * z / fx;
    o[12] = (by - ppy) * z / fy;
    o[13] = z;
}

// ---------------- launch ------------------------------------------------------
extern "C" void kernel_launch(void* const* d_in, const int* in_sizes, int n_in,
                              void* d_out, int out_size) {
    const int*   label   = (const int*)  d_in[0];   // (1,240,320) int32
    const float* vp      = (const float*)d_in[1];   // (1,66,240,320) f32
    const float* extents = (const float*)d_in[2];   // (22,3) f32
    const float* poses   = (const float*)d_in[3];   // (22,13) f32
    const float* mdata   = (const float*)d_in[4];   // (1,9) f32
    float*       out     = (float*)d_out;           // (1,22,14) f32

    k_pre   <<<PP / 256, 256>>>(label, vp);
    k_vote  <<<VBLKS, VTHR>>>();
    k_argmax<<<1, NC * 32>>>();
    k_zsum  <<<PP / 256, 256>>>();
    k_final <<<1, 32>>>(extents, poses, mdata, out);
}

// round 3
// speedup vs baseline: 2.1025x; 1.3971x over previous
#include <cuda_runtime.h>
#include <cuda_bf16.h>

#define PP     76800     // H*W
#define HH     240
#define WW     320
#define NC     22        // classes
#define NCP    11        // class pairs (u64 packing)
#define NQ     300       // query points (15*20)
#define QW     20        // queries per row
#define QSKIP  16
#define EPSF   1e-6f
#define C1F    (0.9f * 1e-6f)

#define CPAD   23        // padded class stride
#define VTHR   640       // k_vote threads (2 half-blocks of 320)
#define VROWS  2
#define VBLKS  (HH / VROWS)   // 120
#define RTHR   704       // k_reduce threads (22 warps)
#define RBLKS  VBLKS          // 120 blocks x 640 px

// ---------------- device scratch (zero-init; restored to zero every launch) --
__device__ float4             g_pix[PP];          // ux, uy, dz, lab(bits)
__device__ unsigned long long g_accP[NQ * NCP];   // packed vote counts
__device__ int                g_clsCnt[NC];
__device__ float              g_zsum[NC];
__device__ int                g_done;

// ---------------- shared inlier test (identical rounding in vote & reduce) ---
// Equivalent (in reals) to  (cx*ux+cy*uy)/(sqrt(cx^2+cy^2)+eps) > 0.9
__device__ __forceinline__ bool itest(float cx, float cy, float ux, float uy) {
    float rhs = fmaf(cx * cx, 0.81f, (0.81f * cy) * cy);
    float t   = fmaf(cx, ux, fmaf(cy, uy, -C1F));
    return t * fabsf(t) > rhs;
}

// =============== kernel 1: fused per-pixel prep + O(Q*P) vote ================
// 120 blocks, 640 threads. Block owns 2 image rows (640 px). Threads 0..319
// are 300 queries scanning row 0; threads 320..639 the same queries on row 1.
// Private u16 smem histograms -> no atomics in the hot loop.
__global__ void __launch_bounds__(VTHR) k_vote(const int* __restrict__ label,
                                               const float* __restrict__ vp) {
    __shared__ float2         sU[VTHR];              // (ux, uy) per pixel
    __shared__ unsigned short sLab[VTHR];
    __shared__ unsigned short sCnt[2 * NQ * CPAD];   // 27.6 KB

    int t = threadIdx.x;
    #pragma unroll
    for (int i = t; i < 2 * NQ * CPAD; i += VTHR) sCnt[i] = 0;

    // --- prep: one pixel per thread, straight from inputs ---
    int base = blockIdx.x * VTHR;
    int p    = base + t;
    int lab  = label[p];
    float ux = 0.0f, uy = 0.0f, dz = 0.0f;
    if (lab > 0) {
        float dx = vp[(3 * lab + 0) * PP + p];
        float dy = vp[(3 * lab + 1) * PP + p];
        dz       = vp[(3 * lab + 2) * PP + p];
        float dn = sqrtf(dx * dx + dy * dy) + EPSF;
        ux = dx / dn;
        uy = dy / dn;
    }
    sU[t]   = make_float2(ux, uy);
    sLab[t] = (unsigned short)lab;
    g_pix[p] = make_float4(ux, uy, dz, __int_as_float(lab));  // for k_reduce
    __syncthreads();

    // --- vote ---
    int half = t / 320;          // which of the 2 rows
    int tq   = t - half * 320;   // query id within half
    if (tq < NQ) {
        float qx = (float)((tq % QW) * QSKIP);
        float qy = (float)((tq / QW) * QSKIP);
        float cy = qy - (float)(blockIdx.x * VROWS + half);
        float K  = (0.81f * cy) * cy;                 // loop-invariant
        float mC = fmaf(cy, 0.0f, 0.0f);              // (no-op; keep regs tight)
        (void)mC;
        unsigned short* myC = &sCnt[(half * NQ + tq) * CPAD];
        const float2*         su = &sU[half * 320];
        const unsigned short* sl = &sLab[half * 320];
        float cx = qx;
        #pragma unroll 8
        for (int i = 0; i < WW; i++) {
            float2 u  = su[i];                        // smem broadcast
            float rhs = fmaf(cx * cx, 0.81f, K);
            float tt  = fmaf(cx, u.x, fmaf(cy, u.y, -C1F));
            if (tt * fabsf(tt) > rhs)
                myC[sl[i]] += 1;                      // private row, no atomic
            cx -= 1.0f;                               // exact small ints
        }
    }
    __syncthreads();

    // --- flush: merge the two half-rows, pack class pairs into u64 REDs ---
    if (t < NQ) {
        #pragma unroll
        for (int c = 0; c < NCP; c++) {
            unsigned int lo = (unsigned int)sCnt[t * CPAD + 2 * c]
                            + (unsigned int)sCnt[(NQ + t) * CPAD + 2 * c];
            unsigned int hi = (unsigned int)sCnt[t * CPAD + 2 * c + 1]
                            + (unsigned int)sCnt[(NQ + t) * CPAD + 2 * c + 1];
            unsigned long long v = (unsigned long long)lo
                                 | ((unsigned long long)hi << 32);
            if (v) atomicAdd(&g_accP[t * NCP + c], v);   // exact int sums
        }
    }
}

// =============== kernel 2: fused argmax + z-sum + final + cleanup ============
__global__ void __launch_bounds__(RTHR) k_reduce(const float* __restrict__ extents,
                                                 const float* __restrict__ poses,
                                                 const float* __restrict__ mdata,
                                                 float* __restrict__ out) {
    __shared__ float sA[NQ * NC];    // 26.4 KB vote table [q][c]
    __shared__ int   sBQ[NC];
    __shared__ float sBV[NC];
    __shared__ float sZ[NC];
    __shared__ int   sCC[NC];
    __shared__ int   sLast;

    int t = threadIdx.x;
    if (t < NC) { sZ[t] = 0.0f; sCC[t] = 0; }
    if (t == 0) sLast = 0;

    // --- stage vote table (coalesced; L2-broadcast across blocks) ---
    for (int i = t; i < NQ * NCP; i += RTHR) {
        unsigned long long v = g_accP[i];
        int q = i / NCP, c = i % NCP;
        *reinterpret_cast<float2*>(&sA[q * NC + 2 * c]) =
            make_float2((float)(unsigned int)v, (float)(unsigned int)(v >> 32));
    }
    __syncthreads();

    // --- per-class argmax: warp w owns class w (first-index ties) ---
    {
        int w = t >> 5, lane = t & 31;
        float best = -1.0f;
        int   bq   = 0;
        for (int q = lane; q < NQ; q += 32) {
            float v = sA[q * NC + w];
            if (v > best) { best = v; bq = q; }
        }
        #pragma unroll
        for (int off = 16; off; off >>= 1) {
            float ov = __shfl_down_sync(0xffffffffu, best, off);
            int   oq = __shfl_down_sync(0xffffffffu, bq,   off);
            if (ov > best || (ov == best && oq < bq)) { best = ov; bq = oq; }
        }
        if (lane == 0) { sBQ[w] = bq; sBV[w] = best; }
    }
    __syncthreads();

    // --- z-sum + class counts over this block's 640 pixels ---
    if (t < VTHR) {
        int p = blockIdx.x * VTHR + t;
        float4 pv = g_pix[p];
        int lab = __float_as_int(pv.w);
        atomicAdd(&sCC[lab], 1);
        if (lab > 0) {
            int q = sBQ[lab];
            float qx = (float)((q % QW) * QSKIP);
            float qy = (float)((q / QW) * QSKIP);
            float cx = qx - (float)(p % WW);
            float cy = qy - (float)(p / WW);
            if (itest(cx, cy, pv.x, pv.y))        // same rounding as k_vote
                atomicAdd(&sZ[lab], pv.z);
        }
    }
    __syncthreads();

    if (t < NC) {
        if (sCC[t])        atomicAdd(&g_clsCnt[t], sCC[t]);
        if (sZ[t] != 0.0f) atomicAdd(&g_zsum[t], sZ[t]);
    }
    __threadfence();
    __syncthreads();
    if (t == 0) {
        int ticket = atomicAdd(&g_done, 1);
        if (ticket == RBLKS - 1) sLast = 1;
    }
    __syncthreads();
    if (!sLast) return;

    // ================= last block: assemble output + reset scratch ===========
    if (t < NC) {
        __threadfence();     // acquire published g_zsum / g_clsCnt
        int c = t;
        float fx  = mdata[0] + EPSF;
        float fy  = mdata[4] + EPSF;
        float ppx = mdata[2];
        float ppy = mdata[5];

        float bv = sBV[c];
        int   bq = sBQ[c];
        float bx = (float)((bq % QW) * QSKIP);
        float by = (float)((bq / QW) * QSKIP);

        float cc = (float)g_clsCnt[c];
        float z  = g_zsum[c] / (bv + EPSF);   // cnt == best_votes (identity)

        float ex = extents[c * 3 + 0];
        float ey = extents[c * 3 + 1];
        float ez = extents[c * 3 + 2];
        float half = 0.5f * sqrtf(ex * ex + ey * ey + ez * ez);

        float zsafe = (fabsf(z) > EPSF) ? z : EPSF;
        float r = fx * half / zsafe;

        bool valid = (bv >= 50.0f) && (cc >= 500.0f) && (bv / (cc + EPSF) >= 0.02f);
        float score = valid ? bv : 0.0f;

        float* o = out + c * 14;
        o[0]  = 0.0f;
        o[1]  = (float)c;
        o[2]  = bx - r;
        o[3]  = by - r;
        o[4]  = bx + r;
        o[5]  = by + r;
        o[6]  = score;
        o[7]  = poses[c * 13 + 6];
        o[8]  = poses[c * 13 + 7];
        o[9]  = poses[c * 13 + 8];
        o[10] = poses[c * 13 + 9];
        o[11] = (bx - ppx) * z / fx;
        o[12] = (by - ppy) * z / fy;
        o[13] = z;

        // reset per-launch accumulators for the next graph replay
        g_clsCnt[c] = 0;
        g_zsum[c]   = 0.0f;
    }
    for (int i = t; i < NQ * NCP; i += RTHR) g_accP[i] = 0ULL;
    if (t == 0) g_done = 0;
}

// ---------------- launch ------------------------------------------------------
extern "C" void kernel_launch(void* const* d_in, const int* in_sizes, int n_in,
                              void* d_out, int out_size) {
    const int*   label   = (const int*)  d_in[0];   // (1,240,320) int32
    const float* vp      = (const float*)d_in[1];   // (1,66,240,320) f32
    const float* extents = (const float*)d_in[2];   // (22,3) f32
    const float* poses   = (const float*)d_in[3];   // (22,13) f32
    const float* mdata   = (const float*)d_in[4];   // (1,9) f32
    float*       out     = (float*)d_out;           // (1,22,14) f32

    k_vote  <<<VBLKS, VTHR>>>(label, vp);
    k_reduce<<<RBLKS, RTHR>>>(extents, poses, mdata, out);
}

// round 4
// speedup vs baseline: 2.6691x; 1.2695x over previous
#include <cuda_runtime.h>
#include <cuda_bf16.h>

#define PP     76800     // H*W
#define HH     240
#define WW     320
#define NC     22        // classes
#define NG     6         // u64 groups of 4 u16 class lanes (24 >= 22)
#define NGP    7         // padded row stride in u64 (56B -> 2-way max conflicts)
#define NQ     300       // query points (15*20)
#define QW     20        // queries per row
#define QSKIP  16
#define EPSF   1e-6f
#define C1F    (0.9f * 1e-6f)

#define VTHR   640            // k_vote threads (2 copies of 300 queries)
#define VBLKS  HH             // 240 blocks, one image row each
#define RTHR   704            // k_reduce threads (22 warps)
#define RBLKS  240            // k_reduce blocks, 320 px each

// ---------------- device scratch (zero-init; restored to zero every launch) --
__device__ float4             g_pix[PP];        // ux, uy, dz, lab(bits)
__device__ unsigned long long g_accP[NQ * NG];  // votes: 4 u16 class lanes / u64
__device__ int                g_clsCnt[NC];
__device__ float              g_zsum[NC];
__device__ int                g_done;

// ---------------- shared inlier test (identical rounding in vote & reduce) ---
// Equivalent (in reals) to  (cx*ux+cy*uy)/(sqrt(cx^2+cy^2)+eps) > 0.9
__device__ __forceinline__ bool itest(float cx, float cy, float ux, float uy) {
    float rhs = fmaf(cx * cx, 0.81f, (0.81f * cy) * cy);
    float t   = fmaf(cx, ux, fmaf(cy, uy, -C1F));
    return t * fabsf(t) > rhs;
}

// =============== kernel 1: fused per-pixel prep + O(Q*P) vote ================
// 240 blocks (1 row), 640 threads: threads 0..299 = queries scanning px 0..159,
// threads 320..619 = same queries scanning px 160..319. Pixels staged in smem
// as pairs; private u64-lane histograms -> no atomics in the hot loop.
__global__ void __launch_bounds__(VTHR) k_vote(const int* __restrict__ label,
                                               const float* __restrict__ vp) {
    __shared__ float4             sU4[WW / 2];          // (ux0,uy0,ux1,uy1)
    __shared__ unsigned int       sLab2[WW / 2];        // two u16 labels
    __shared__ unsigned long long sCnt[2 * NQ * NGP];   // 33.6 KB

    int t = threadIdx.x;
    #pragma unroll
    for (int i = t; i < 2 * NQ * NGP; i += VTHR) sCnt[i] = 0ULL;

    // --- prep: one pixel per thread (threads 0..319) ---
    int row = blockIdx.x;
    if (t < WW) {
        int p   = row * WW + t;
        int lab = label[p];
        float ux = 0.0f, uy = 0.0f, dz = 0.0f;
        if (lab > 0) {
            float dx = vp[(3 * lab + 0) * PP + p];
            float dy = vp[(3 * lab + 1) * PP + p];
            dz       = vp[(3 * lab + 2) * PP + p];
            float dn = sqrtf(dx * dx + dy * dy) + EPSF;
            ux = dx / dn;
            uy = dy / dn;
        }
        reinterpret_cast<float2*>(sU4)[t]         = make_float2(ux, uy);
        reinterpret_cast<unsigned short*>(sLab2)[t] = (unsigned short)lab;
        g_pix[p] = make_float4(ux, uy, dz, __int_as_float(lab));
    }
    __syncthreads();

    // --- vote: 80 pixel-pairs per thread ---
    int copy = (t >= 320);
    int tq   = t - copy * 320;
    if (tq < NQ) {
        float qx = (float)((tq % QW) * QSKIP);
        float qy = (float)((tq / QW) * QSKIP);
        float cy = qy - (float)row;
        float K  = (0.81f * cy) * cy;                       // loop-invariant
        unsigned short* myC =
            reinterpret_cast<unsigned short*>(&sCnt[(copy * NQ + tq) * NGP]);
        int   j0  = copy * 80;
        float cx0 = qx - (float)(2 * j0);
        #pragma unroll 8
        for (int j = 0; j < 80; j++) {
            float4       u    = sU4[j0 + j];                // smem broadcast
            unsigned int lab2 = sLab2[j0 + j];              // smem broadcast
            float rhs0 = fmaf(cx0 * cx0, 0.81f, K);
            float t0   = fmaf(cx0, u.x, fmaf(cy, u.y, -C1F));
            if (t0 * fabsf(t0) > rhs0) myC[lab2 & 0xFFFFu] += 1;
            float cx1  = cx0 - 1.0f;
            float rhs1 = fmaf(cx1 * cx1, 0.81f, K);
            float t1   = fmaf(cx1, u.z, fmaf(cy, u.w, -C1F));
            if (t1 * fabsf(t1) > rhs1) myC[lab2 >> 16] += 1;
            cx0 -= 2.0f;                                    // exact small ints
        }
    }
    __syncthreads();

    // --- flush: merge copies (u64 lane add, no carry: lanes <= 320) + RED ---
    if (t < NQ) {
        #pragma unroll
        for (int g = 0; g < NG; g++) {
            unsigned long long v = sCnt[t * NGP + g] + sCnt[(NQ + t) * NGP + g];
            if (v) atomicAdd(&g_accP[t * NG + g], v);       // exact u16 lanes
        }
    }
}

// =============== kernel 2: fused argmax + z-sum + final + cleanup ============
__global__ void __launch_bounds__(RTHR) k_reduce(const float* __restrict__ extents,
                                                 const float* __restrict__ poses,
                                                 const float* __restrict__ mdata,
                                                 float* __restrict__ out) {
    __shared__ float sA[NG * 4 * NQ];   // 28.8 KB vote table, [c][q] layout
    __shared__ int   sBQ[NC];
    __shared__ float sBV[NC];
    __shared__ float sZ[NC];
    __shared__ int   sCC[NC];
    __shared__ int   sLast;

    int t = threadIdx.x;
    if (t < NC) { sZ[t] = 0.0f; sCC[t] = 0; }
    if (t == 0) sLast = 0;

    // --- stage vote table: unpack u16 lanes -> float, transpose to [c][q] ---
    for (int i = t; i < NQ * NG; i += RTHR) {
        unsigned long long v = g_accP[i];                   // coalesced u64
        int q = i / NG, g = i - q * NG;
        #pragma unroll
        for (int j = 0; j < 4; j++)
            sA[(4 * g + j) * NQ + q] =
                (float)((unsigned int)(v >> (16 * j)) & 0xFFFFu);
    }
    __syncthreads();

    // --- per-class argmax: warp w owns class w (first-index ties) ---
    {
        int w = t >> 5, lane = t & 31;
        if (w < NC) {
            float best = -1.0f;
            int   bq   = 0;
            const float* col = &sA[w * NQ];
            for (int q = lane; q < NQ; q += 32) {           // conflict-free
                float v = col[q];
                if (v > best) { best = v; bq = q; }
            }
            #pragma unroll
            for (int off = 16; off; off >>= 1) {
                float ov = __shfl_down_sync(0xffffffffu, best, off);
                int   oq = __shfl_down_sync(0xffffffffu, bq,   off);
                if (ov > best || (ov == best && oq < bq)) { best = ov; bq = oq; }
            }
            if (lane == 0) { sBQ[w] = bq; sBV[w] = best; }
        }
    }
    __syncthreads();

    // --- z-sum + class counts over this block's 320 pixels ---
    if (t < WW) {
        int p = blockIdx.x * WW + t;
        float4 pv = g_pix[p];
        int lab = __float_as_int(pv.w);
        atomicAdd(&sCC[lab], 1);
        if (lab > 0) {
            int q = sBQ[lab];
            float qx = (float)((q % QW) * QSKIP);
            float qy = (float)((q / QW) * QSKIP);
            float cx = qx - (float)t;                // t == column in this row
            float cy = qy - (float)blockIdx.x;
            if (itest(cx, cy, pv.x, pv.y))           // same rounding as k_vote
                atomicAdd(&sZ[lab], pv.z);
        }
    }
    __syncthreads();

    if (t < NC) {
        if (sCC[t])        atomicAdd(&g_clsCnt[t], sCC[t]);
        if (sZ[t] != 0.0f) atomicAdd(&g_zsum[t], sZ[t]);
    }
    __threadfence();
    __syncthreads();
    if (t == 0) {
        int ticket = atomicAdd(&g_done, 1);
        if (ticket == RBLKS - 1) sLast = 1;
    }
    __syncthreads();
    if (!sLast) return;

    // ================= last block: assemble output + reset scratch ===========
    if (t < NC) {
        __threadfence();     // acquire published g_zsum / g_clsCnt
        int c = t;
        float fx  = mdata[0] + EPSF;
        float fy  = mdata[4] + EPSF;
        float ppx = mdata[2];
        float ppy = mdata[5];

        float bv = sBV[c];
        int   bq = sBQ[c];
        float bx = (float)((bq % QW) * QSKIP);
        float by = (float)((bq / QW) * QSKIP);

        float cc = (float)g_clsCnt[c];
        float z  = g_zsum[c] / (bv + EPSF);   // cnt == best_votes (identity)

        float ex = extents[c * 3 + 0];
        float ey = extents[c * 3 + 1];
        float ez = extents[c * 3 + 2];
        float half = 0.5f * sqrtf(ex * ex + ey * ey + ez * ez);

        float zsafe = (fabsf(z) > EPSF) ? z : EPSF;
        float r = fx * half / zsafe;

        bool valid = (bv >= 50.0f) && (cc >= 500.0f) && (bv / (cc + EPSF) >= 0.02f);
        float score = valid ? bv : 0.0f;

        float* o = out + c * 14;
        o[0]  = 0.0f;
        o[1]  = (float)c;
        o[2]  = bx - r;
        o[3]  = by - r;
        o[4]  = bx + r;
        o[5]  = by + r;
        o[6]  = score;
        o[7]  = poses[c * 13 + 6];
        o[8]  = poses[c * 13 + 7];
        o[9]  = poses[c * 13 + 8];
        o[10] = poses[c * 13 + 9];
        o[11] = (bx - ppx) * z / fx;
        o[12] = (by - ppy) * z / fy;
        o[13] = z;

        // reset per-launch accumulators for the next graph replay
        g_clsCnt[c] = 0;
        g_zsum[c]   = 0.0f;
    }
    for (int i = t; i < NQ * NG; i += RTHR) g_accP[i] = 0ULL;
    if (t == 0) g_done = 0;
}

// ---------------- launch ------------------------------------------------------
extern "C" void kernel_launch(void* const* d_in, const int* in_sizes, int n_in,
                              void* d_out, int out_size) {
    const int*   label   = (const int*)  d_in[0];   // (1,240,320) int32
    const float* vp      = (const float*)d_in[1];   // (1,66,240,320) f32
    const float* extents = (const float*)d_in[2];   // (22,3) f32
    const float* poses   = (const float*)d_in[3];   // (22,13) f32
    const float* mdata   = (const float*)d_in[4];   // (1,9) f32
    float*       out     = (float*)d_out;           // (1,22,14) f32

    k_vote  <<<VBLKS, VTHR>>>(label, vp);
    k_reduce<<<RBLKS, RTHR>>>(extents, poses, mdata, out);
}